// round 9
// baseline (speedup 1.0000x reference)
#include <cuda_runtime.h>
#include <cuda_bf16.h>
#include <math_constants.h>
#include <cstdint>

#define B_TOK 8192
#define HDIM  7168
#define NEXP  256
#define NGRP  8
#define TOPKG 4
#define TOPK  8
#define SCALE 2.5f
#define EPS   1e-20f

// ---------------- static device scratch (allocation-free rule) -------------
__device__ __nv_bfloat16 g_wh[(size_t)NEXP * HDIM];   // transposed [E][H]
__device__ __nv_bfloat16 g_wl[(size_t)NEXP * HDIM];

// ---------------- weight conversion ----------------------------------------
__global__ void convert_w_kernel(const float* __restrict__ w) {
    __shared__ float tile[32][33];
    const int k0 = blockIdx.x * 32, e0 = blockIdx.y * 32;
    const int tx = threadIdx.x, ty = threadIdx.y;   // block (32,8)
#pragma unroll
    for (int j = 0; j < 4; j++)
        tile[ty + j * 8][tx] = w[(size_t)(k0 + ty + j * 8) * NEXP + e0 + tx];
    __syncthreads();
#pragma unroll
    for (int j = 0; j < 4; j++) {
        float v = tile[tx][ty + j * 8];
        __nv_bfloat16 h = __float2bfloat16(v);
        size_t o = (size_t)(e0 + ty + j * 8) * HDIM + k0 + tx;
        g_wh[o] = h;
        g_wl[o] = __float2bfloat16(v - __bfloat162float(h));
    }
}

// ---------------- fused GEMM (M=64 x N=256) + in-CTA routing ---------------
#define BK      64
#define PITCH   144                         // bytes per smem row
#define A_SM    (64 * PITCH)                // 9216
#define B_SM    (256 * PITCH)               // 36864
#define STAGE_B (2 * A_SM + 2 * B_SM)       // xh,xl,wh,wl = 92160
#define NSTAGE  2
#define SMEM_GEMM (NSTAGE * STAGE_B)        // 184320
#define NCHUNK  (HDIM / BK)                 // 112
#define LPITCH  264                         // smem logits pitch (floats)

__device__ __forceinline__ uint32_t smem_u32(const void* p) {
    uint32_t a;
    asm("{ .reg .u64 t; cvta.to.shared.u64 t, %1; cvt.u32.u64 %0, t; }" : "=r"(a) : "l"(p));
    return a;
}
#define CP_ASYNC16(dst, src) \
    asm volatile("cp.async.cg.shared.global [%0], [%1], 16;" :: "r"(dst), "l"(src) : "memory")
#define CP_COMMIT() asm volatile("cp.async.commit_group;" ::: "memory")
#define CP_WAIT1()  asm volatile("cp.async.wait_group 1;" ::: "memory")

#define STS128(a, r0, r1, r2, r3) \
    asm volatile("st.shared.v4.b32 [%0], {%1,%2,%3,%4};" \
        :: "r"(a), "r"(r0), "r"(r1), "r"(r2), "r"(r3) : "memory")

#define LDMATRIX_X4(r0, r1, r2, r3, a) \
    asm volatile("ldmatrix.sync.aligned.m8n8.x4.shared.b16 {%0,%1,%2,%3}, [%4];" \
        : "=r"(r0), "=r"(r1), "=r"(r2), "=r"(r3) : "r"(a))

#define MMA_BF16(c, a, b0, b1) \
    asm volatile("mma.sync.aligned.m16n8k16.row.col.f32.bf16.bf16.f32 " \
        "{%0,%1,%2,%3}, {%4,%5,%6,%7}, {%8,%9}, {%0,%1,%2,%3};" \
        : "+f"((c)[0]), "+f"((c)[1]), "+f"((c)[2]), "+f"((c)[3]) \
        : "r"((a)[0]), "r"((a)[1]), "r"((a)[2]), "r"((a)[3]), "r"(b0), "r"(b1))

__device__ __forceinline__ uint32_t pack_bf16(float f0, float f1) {
    __nv_bfloat162 p;
    p.x = __float2bfloat16(f0);
    p.y = __float2bfloat16(f1);
    return *(uint32_t*)&p;
}

__global__ __launch_bounds__(512, 1) void gemm_kernel(const float* __restrict__ x,
                                                      const float* __restrict__ bias,
                                                      float* __restrict__ out,
                                                      int out_size) {
    extern __shared__ char smem[];
    const uint32_t sbase = smem_u32(smem);
    const int tid  = threadIdx.x;
    const int wid  = tid >> 5;
    const int lane = tid & 31;
    const int m0   = blockIdx.x * 64;
    const int wm   = (wid & 1) * 32;       // warp tile 32(M) x 32(N)
    const int wn   = (wid >> 1) * 32;

    float acc[2][4][4];
#pragma unroll
    for (int mt = 0; mt < 2; mt++)
#pragma unroll
        for (int nt = 0; nt < 4; nt++)
#pragma unroll
            for (int r = 0; r < 4; r++) acc[mt][nt][r] = 0.f;

    const int a_row = ((lane >> 3) & 1) * 8 + (lane & 7);
    const int a_k   = ((lane >> 4) & 1) * 8;
    const int b_row = ((lane >> 4) & 1) * 8 + (lane & 7);
    const int b_k   = ((lane >> 3) & 1) * 8;

    // A producer: row = tid>>3 (0..63), seg = tid&7 (8 floats = 32B fp32, 16B bf16)
    const int arow_p = tid >> 3;
    const int aseg   = tid & 7;
    // B producer: row = tid>>1 (0..255), half = tid&1 (64B)
    const int brow_p = tid >> 1;
    const int bhalf  = tid & 1;

    auto ldgA = [&](int chunk, float4* buf) {
        const float* p = x + (size_t)(m0 + arow_p) * HDIM + chunk * BK + aseg * 8;
        buf[0] = *(const float4*)(p);
        buf[1] = *(const float4*)(p + 4);
    };
    auto stsA = [&](int stage, const float4* buf) {
        const float* a = (const float*)buf;
        uint32_t hh[4], ll[4];
#pragma unroll
        for (int j = 0; j < 4; j++) {
            float f0 = a[2 * j], f1 = a[2 * j + 1];
            __nv_bfloat16 h0 = __float2bfloat16(f0);
            __nv_bfloat16 h1 = __float2bfloat16(f1);
            hh[j] = ((uint32_t)*(uint16_t*)&h0) | ((uint32_t)*(uint16_t*)&h1 << 16);
            ll[j] = pack_bf16(f0 - __bfloat162float(h0), f1 - __bfloat162float(h1));
        }
        const uint32_t xh_s = sbase + stage * STAGE_B + arow_p * PITCH + aseg * 16;
        STS128(xh_s,        hh[0], hh[1], hh[2], hh[3]);
        STS128(xh_s + A_SM, ll[0], ll[1], ll[2], ll[3]);
    };
    auto cpB = [&](int chunk, int stage) {
        const size_t gof = (size_t)brow_p * HDIM + chunk * BK + bhalf * 32;
        const __nv_bfloat16* wh = g_wh + gof;
        const __nv_bfloat16* wl = g_wl + gof;
        const uint32_t whs = sbase + stage * STAGE_B + 2 * A_SM + brow_p * PITCH + bhalf * 64;
        const uint32_t wls = whs + B_SM;
#pragma unroll
        for (int c = 0; c < 4; c++) {
            CP_ASYNC16(whs + c * 16, wh + c * 8);
            CP_ASYNC16(wls + c * 16, wl + c * 8);
        }
    };

    // prologue
    float4 abuf[2];
    {
        float4 t[2];
        ldgA(0, t); stsA(0, t); cpB(0, 0); CP_COMMIT();
        ldgA(1, t); stsA(1, t); cpB(1, 1); CP_COMMIT();
        ldgA(2, abuf);
    }

    for (int i = 0; i < NCHUNK; i++) {
        CP_WAIT1();
        __syncthreads();

        const int s = i & 1;
        const uint32_t Ah = sbase + s * STAGE_B;
        const uint32_t Al = Ah + A_SM;
        const uint32_t Bh = Ah + 2 * A_SM;
        const uint32_t Bl = Bh + B_SM;
#pragma unroll
        for (int ki = 0; ki < BK; ki += 16) {
            uint32_t ah[2][4], al[2][4], bb[2][4];
#pragma unroll
            for (int mt = 0; mt < 2; mt++) {
                const uint32_t ro = (wm + mt * 16 + a_row) * PITCH + (a_k + ki) * 2;
                LDMATRIX_X4(ah[mt][0], ah[mt][1], ah[mt][2], ah[mt][3], Ah + ro);
                LDMATRIX_X4(al[mt][0], al[mt][1], al[mt][2], al[mt][3], Al + ro);
            }
#pragma unroll
            for (int g = 0; g < 2; g++) {
                const uint32_t ro = (wn + g * 16 + b_row) * PITCH + (b_k + ki) * 2;
                LDMATRIX_X4(bb[g][0], bb[g][1], bb[g][2], bb[g][3], Bh + ro);
            }
            // hh + lh terms (both consume bh)
#pragma unroll
            for (int mt = 0; mt < 2; mt++)
#pragma unroll
                for (int g = 0; g < 2; g++) {
                    MMA_BF16(acc[mt][2 * g],     ah[mt], bb[g][0], bb[g][1]);
                    MMA_BF16(acc[mt][2 * g + 1], ah[mt], bb[g][2], bb[g][3]);
                }
#pragma unroll
            for (int mt = 0; mt < 2; mt++)
#pragma unroll
                for (int g = 0; g < 2; g++) {
                    MMA_BF16(acc[mt][2 * g],     al[mt], bb[g][0], bb[g][1]);
                    MMA_BF16(acc[mt][2 * g + 1], al[mt], bb[g][2], bb[g][3]);
                }
            // hl term (reload B frags as bl, reusing registers)
#pragma unroll
            for (int g = 0; g < 2; g++) {
                const uint32_t ro = (wn + g * 16 + b_row) * PITCH + (b_k + ki) * 2;
                LDMATRIX_X4(bb[g][0], bb[g][1], bb[g][2], bb[g][3], Bl + ro);
            }
#pragma unroll
            for (int mt = 0; mt < 2; mt++)
#pragma unroll
                for (int g = 0; g < 2; g++) {
                    MMA_BF16(acc[mt][2 * g],     ah[mt], bb[g][0], bb[g][1]);
                    MMA_BF16(acc[mt][2 * g + 1], ah[mt], bb[g][2], bb[g][3]);
                }
        }
        __syncthreads();
        if (i + 2 < NCHUNK) { stsA(s, abuf); cpB(i + 2, s); }
        CP_COMMIT();
        if (i + 3 < NCHUNK) ldgA(i + 3, abuf);
    }

    // ---- epilogue: logits -> smem (alias pipeline memory) ----
    __syncthreads();
    float* L = (float*)smem;
#pragma unroll
    for (int mt = 0; mt < 2; mt++) {
        const int lr = wm + mt * 16 + (lane >> 2);
#pragma unroll
        for (int nt = 0; nt < 4; nt++) {
            const int lc = wn + nt * 8 + (lane & 3) * 2;
            *(float2*)&L[(size_t)lr * LPITCH + lc]       = *(float2*)&acc[mt][nt][0];
            *(float2*)&L[(size_t)(lr + 8) * LPITCH + lc] = *(float2*)&acc[mt][nt][2];
        }
    }
    __syncthreads();

    // ---- in-CTA routing: warp wid handles tokens m0 + wid*4 .. +3 ----
#pragma unroll
    for (int t = 0; t < 4; t++) {
        const int tok_l = wid * 4 + t;
        const float* lg = L + (size_t)tok_l * LPITCH;

        float v[NGRP];
#pragma unroll
        for (int j = 0; j < NGRP; j++) v[j] = lg[lane + 32 * j];

        float m = v[0];
#pragma unroll
        for (int j = 1; j < NGRP; j++) m = fmaxf(m, v[j]);
#pragma unroll
        for (int o = 16; o > 0; o >>= 1) m = fmaxf(m, __shfl_xor_sync(0xffffffffu, m, o));
        float s = 0.f, sc[NGRP];
#pragma unroll
        for (int j = 0; j < NGRP; j++) { sc[j] = __expf(v[j] - m); s += sc[j]; }
#pragma unroll
        for (int o = 16; o > 0; o >>= 1) s += __shfl_xor_sync(0xffffffffu, s, o);
        const float inv = 1.f / s;

        float swb[NGRP];
#pragma unroll
        for (int j = 0; j < NGRP; j++) { sc[j] *= inv; swb[j] = sc[j] + bias[lane + 32 * j]; }

        float gscore[NGRP];
#pragma unroll
        for (int j = 0; j < NGRP; j++) {
            float m1 = swb[j]; int l1 = lane;
#pragma unroll
            for (int o = 16; o > 0; o >>= 1) {
                float om = __shfl_xor_sync(0xffffffffu, m1, o);
                int   ol = __shfl_xor_sync(0xffffffffu, l1, o);
                if (om > m1 || (om == m1 && ol < l1)) { m1 = om; l1 = ol; }
            }
            float x2 = (lane == l1) ? -CUDART_INF_F : swb[j];
#pragma unroll
            for (int o = 16; o > 0; o >>= 1) x2 = fmaxf(x2, __shfl_xor_sync(0xffffffffu, x2, o));
            gscore[j] = m1 + x2;
        }

        float gtmp[NGRP]; bool gsel[NGRP];
#pragma unroll
        for (int j = 0; j < NGRP; j++) { gtmp[j] = gscore[j]; gsel[j] = false; }
#pragma unroll
        for (int tt = 0; tt < TOPKG; tt++) {
            int best = 0; float bv = -CUDART_INF_F;
#pragma unroll
            for (int j = 0; j < NGRP; j++)
                if (gtmp[j] > bv) { bv = gtmp[j]; best = j; }
            gsel[best] = true; gtmp[best] = -CUDART_INF_F;
        }

        float masked[NGRP];
#pragma unroll
        for (int j = 0; j < NGRP; j++) masked[j] = gsel[j] ? swb[j] : -CUDART_INF_F;

        float wv[TOPK]; int widx[TOPK]; float wsum = 0.f;
#pragma unroll
        for (int tt = 0; tt < TOPK; tt++) {
            float bv = masked[0]; int bj = 0;
#pragma unroll
            for (int j = 1; j < NGRP; j++)
                if (masked[j] > bv) { bv = masked[j]; bj = j; }
            float mv = bv; int me = lane + 32 * bj;
#pragma unroll
            for (int o = 16; o > 0; o >>= 1) {
                float omv = __shfl_xor_sync(0xffffffffu, mv, o);
                int   ome = __shfl_xor_sync(0xffffffffu, me, o);
                if (omv > mv || (omv == mv && ome < me)) { mv = omv; me = ome; }
            }
            const int wl = me & 31, wj = me >> 5;
            float myv = sc[0];
#pragma unroll
            for (int j = 1; j < NGRP; j++) if (wj == j) myv = sc[j];
            float score = __shfl_sync(0xffffffffu, myv, wl);
            if (lane == wl) {
#pragma unroll
                for (int j = 0; j < NGRP; j++) if (wj == j) masked[j] = -CUDART_INF_F;
            }
            wv[tt] = score; widx[tt] = me; wsum += score;
        }

        if (lane == 0) {
            const int token = m0 + tok_l;
            const float invw = 1.f / wsum;
#pragma unroll
            for (int tt = 0; tt < TOPK; tt++)
                out[(size_t)token * TOPK + tt] = (wv[tt] * invw + EPS) * SCALE;
            if (out_size >= 2 * B_TOK * TOPK) {
#pragma unroll
                for (int tt = 0; tt < TOPK; tt++)
                    out[(size_t)B_TOK * TOPK + (size_t)token * TOPK + tt] = (float)widx[tt];
            }
        }
    }
}

// ---------------------------------------------------------------------------
extern "C" void kernel_launch(void* const* d_in, const int* in_sizes, int n_in,
                              void* d_out, int out_size) {
    const float* x    = (const float*)d_in[0];
    const float* w    = (const float*)d_in[1];
    const float* bias = (const float*)d_in[2];
    float* out = (float*)d_out;

    cudaFuncSetAttribute(gemm_kernel, cudaFuncAttributeMaxDynamicSharedMemorySize, SMEM_GEMM);

    convert_w_kernel<<<dim3(HDIM / 32, NEXP / 32), dim3(32, 8)>>>(w);
    gemm_kernel<<<B_TOK / 64, 512, SMEM_GEMM>>>(x, bias, out, out_size);
}

// round 10
// speedup vs baseline: 1.0808x; 1.0808x over previous
#include <cuda_runtime.h>
#include <cuda_bf16.h>
#include <math_constants.h>
#include <cstdint>

#define B_TOK 8192
#define HDIM  7168
#define NEXP  256
#define NGRP  8
#define TOPKG 4
#define TOPK  8
#define SCALE 2.5f
#define EPS   1e-20f

// ---------------- static device scratch (allocation-free rule) -------------
__device__ __nv_bfloat16 g_wh[(size_t)NEXP * HDIM];   // transposed [E][H]
__device__ __nv_bfloat16 g_wl[(size_t)NEXP * HDIM];
__device__ float g_logits[(size_t)B_TOK * NEXP];

// ---------------- weight conversion ----------------------------------------
__global__ void convert_w_kernel(const float* __restrict__ w) {
    __shared__ float tile[32][33];
    const int k0 = blockIdx.x * 32, e0 = blockIdx.y * 32;
    const int tx = threadIdx.x, ty = threadIdx.y;   // block (32,8)
#pragma unroll
    for (int j = 0; j < 4; j++)
        tile[ty + j * 8][tx] = w[(size_t)(k0 + ty + j * 8) * NEXP + e0 + tx];
    __syncthreads();
#pragma unroll
    for (int j = 0; j < 4; j++) {
        float v = tile[tx][ty + j * 8];
        __nv_bfloat16 h = __float2bfloat16(v);
        size_t o = (size_t)(e0 + ty + j * 8) * HDIM + k0 + tx;
        g_wh[o] = h;
        g_wl[o] = __float2bfloat16(v - __bfloat162float(h));
    }
}

// ---------------- fused split + bf16 mma.sync GEMM --------------------------
// CTA 128x128, 16 warps of 32x32, BK=64, 3-stage pipeline.
#define BK      64
#define PITCH   144
#define TILE_SM (128 * PITCH)              // 18432
#define STAGE_B (4 * TILE_SM)              // xh, xl, wh, wl = 73728
#define NSTAGE  3
#define SMEM_GEMM (NSTAGE * STAGE_B)       // 221184
#define NCHUNK  (HDIM / BK)                // 112

__device__ __forceinline__ uint32_t smem_u32(const void* p) {
    uint32_t a;
    asm("{ .reg .u64 t; cvta.to.shared.u64 t, %1; cvt.u32.u64 %0, t; }" : "=r"(a) : "l"(p));
    return a;
}
#define CP_ASYNC16(dst, src) \
    asm volatile("cp.async.cg.shared.global [%0], [%1], 16;" :: "r"(dst), "l"(src) : "memory")
#define CP_COMMIT() asm volatile("cp.async.commit_group;" ::: "memory")
#define CP_WAIT1()  asm volatile("cp.async.wait_group 1;" ::: "memory")

#define STS128(a, r0, r1, r2, r3) \
    asm volatile("st.shared.v4.b32 [%0], {%1,%2,%3,%4};" \
        :: "r"(a), "r"(r0), "r"(r1), "r"(r2), "r"(r3) : "memory")

#define LDMATRIX_X4(r0, r1, r2, r3, a) \
    asm volatile("ldmatrix.sync.aligned.m8n8.x4.shared.b16 {%0,%1,%2,%3}, [%4];" \
        : "=r"(r0), "=r"(r1), "=r"(r2), "=r"(r3) : "r"(a))

#define MMA_BF16(c, a, b0, b1) \
    asm volatile("mma.sync.aligned.m16n8k16.row.col.f32.bf16.bf16.f32 " \
        "{%0,%1,%2,%3}, {%4,%5,%6,%7}, {%8,%9}, {%0,%1,%2,%3};" \
        : "+f"((c)[0]), "+f"((c)[1]), "+f"((c)[2]), "+f"((c)[3]) \
        : "r"((a)[0]), "r"((a)[1]), "r"((a)[2]), "r"((a)[3]), "r"(b0), "r"(b1))

__device__ __forceinline__ uint32_t pack_bf16(float f0, float f1) {
    __nv_bfloat162 p;
    p.x = __float2bfloat16(f0);
    p.y = __float2bfloat16(f1);
    return *(uint32_t*)&p;
}

__global__ __launch_bounds__(512, 1) void gemm_kernel(const float* __restrict__ x) {
    extern __shared__ char smem[];
    const uint32_t sbase = smem_u32(smem);
    const int tid  = threadIdx.x;
    const int wid  = tid >> 5;
    const int lane = tid & 31;
    const int m0   = blockIdx.x * 128;
    const int n0   = blockIdx.y * 128;
    const int wm   = (wid & 3) * 32;
    const int wn   = (wid >> 2) * 32;

    float acc[2][4][4];
#pragma unroll
    for (int mt = 0; mt < 2; mt++)
#pragma unroll
        for (int nt = 0; nt < 4; nt++)
#pragma unroll
            for (int r = 0; r < 4; r++) acc[mt][nt][r] = 0.f;

    const int a_row = ((lane >> 3) & 1) * 8 + (lane & 7);
    const int a_k   = ((lane >> 4) & 1) * 8;
    const int b_row = ((lane >> 4) & 1) * 8 + (lane & 7);
    const int b_k   = ((lane >> 3) & 1) * 8;

    const int trow = tid >> 2;
    const int tc16 = (tid & 3) * 16;
    const int bseg = tid & 3;

    auto ldgA = [&](int chunk, float4* buf) {
        const float* p = x + (size_t)(m0 + trow) * HDIM + chunk * BK + tc16;
        buf[0] = *(const float4*)(p);
        buf[1] = *(const float4*)(p + 4);
        buf[2] = *(const float4*)(p + 8);
        buf[3] = *(const float4*)(p + 12);
    };
    auto stsA = [&](int stage, const float4* buf) {
        const float* a = (const float*)buf;
        uint32_t hh[8], ll[8];
#pragma unroll
        for (int j = 0; j < 8; j++) {
            float f0 = a[2 * j], f1 = a[2 * j + 1];
            __nv_bfloat16 h0 = __float2bfloat16(f0);
            __nv_bfloat16 h1 = __float2bfloat16(f1);
            hh[j] = ((uint32_t)*(uint16_t*)&h0) | ((uint32_t)*(uint16_t*)&h1 << 16);
            ll[j] = pack_bf16(f0 - __bfloat162float(h0), f1 - __bfloat162float(h1));
        }
        const uint32_t xh_s = sbase + stage * STAGE_B + trow * PITCH + tc16 * 2;
        const uint32_t xl_s = xh_s + TILE_SM;
        STS128(xh_s,      hh[0], hh[1], hh[2], hh[3]);
        STS128(xh_s + 16, hh[4], hh[5], hh[6], hh[7]);
        STS128(xl_s,      ll[0], ll[1], ll[2], ll[3]);
        STS128(xl_s + 16, ll[4], ll[5], ll[6], ll[7]);
    };
    auto cpB = [&](int chunk, int stage) {
        const size_t gof = (size_t)(n0 + trow) * HDIM + chunk * BK;
        const __nv_bfloat16* wh = g_wh + gof;
        const __nv_bfloat16* wl = g_wl + gof;
        const uint32_t whs = sbase + stage * STAGE_B + 2 * TILE_SM + trow * PITCH;
        const uint32_t wls = whs + TILE_SM;
#pragma unroll
        for (int u = 0; u < 2; u++) {
            const int s = bseg + u * 4;
            CP_ASYNC16(whs + s * 16, wh + s * 8);
            CP_ASYNC16(wls + s * 16, wl + s * 8);
        }
    };

    // prologue
    float4 abuf[4];
    {
        float4 t[4];
        ldgA(0, t); stsA(0, t);
        ldgA(1, t); stsA(1, t);
        cpB(0, 0); CP_COMMIT();
        cpB(1, 1); CP_COMMIT();
        ldgA(2, abuf);
    }

    for (int i = 0; i < NCHUNK; i++) {
        CP_WAIT1();
        __syncthreads();
        if (i + 2 < NCHUNK) stsA((i + 2) % NSTAGE, abuf);
        if (i + 3 < NCHUNK) ldgA(i + 3, abuf);
        if (i + 2 < NCHUNK) cpB(i + 2, (i + 2) % NSTAGE);
        CP_COMMIT();

        const int s = i % NSTAGE;
        const uint32_t Ah = sbase + s * STAGE_B;
        const uint32_t Al = Ah + TILE_SM;
        const uint32_t Bh = Ah + 2 * TILE_SM;
        const uint32_t Bl = Ah + 3 * TILE_SM;
#pragma unroll
        for (int ki = 0; ki < BK; ki += 16) {
            uint32_t ah[2][4], al[2][4], bh[2][4], bl[2][4];
            // batch 1: hi fragments, then hh MMAs (overlap with batch-2 LDSM)
#pragma unroll
            for (int mt = 0; mt < 2; mt++) {
                const uint32_t ro = (wm + mt * 16 + a_row) * PITCH + (a_k + ki) * 2;
                LDMATRIX_X4(ah[mt][0], ah[mt][1], ah[mt][2], ah[mt][3], Ah + ro);
            }
#pragma unroll
            for (int g = 0; g < 2; g++) {
                const uint32_t ro = (wn + g * 16 + b_row) * PITCH + (b_k + ki) * 2;
                LDMATRIX_X4(bh[g][0], bh[g][1], bh[g][2], bh[g][3], Bh + ro);
            }
#pragma unroll
            for (int mt = 0; mt < 2; mt++)
#pragma unroll
                for (int g = 0; g < 2; g++) {
                    MMA_BF16(acc[mt][2 * g],     ah[mt], bh[g][0], bh[g][1]);
                    MMA_BF16(acc[mt][2 * g + 1], ah[mt], bh[g][2], bh[g][3]);
                }
            // batch 2: lo fragments, then lh + hl MMAs
#pragma unroll
            for (int mt = 0; mt < 2; mt++) {
                const uint32_t ro = (wm + mt * 16 + a_row) * PITCH + (a_k + ki) * 2;
                LDMATRIX_X4(al[mt][0], al[mt][1], al[mt][2], al[mt][3], Al + ro);
            }
#pragma unroll
            for (int g = 0; g < 2; g++) {
                const uint32_t ro = (wn + g * 16 + b_row) * PITCH + (b_k + ki) * 2;
                LDMATRIX_X4(bl[g][0], bl[g][1], bl[g][2], bl[g][3], Bl + ro);
            }
#pragma unroll
            for (int mt = 0; mt < 2; mt++)
#pragma unroll
                for (int g = 0; g < 2; g++) {
                    MMA_BF16(acc[mt][2 * g],     al[mt], bh[g][0], bh[g][1]);
                    MMA_BF16(acc[mt][2 * g + 1], al[mt], bh[g][2], bh[g][3]);
                }
#pragma unroll
            for (int mt = 0; mt < 2; mt++)
#pragma unroll
                for (int g = 0; g < 2; g++) {
                    MMA_BF16(acc[mt][2 * g],     ah[mt], bl[g][0], bl[g][1]);
                    MMA_BF16(acc[mt][2 * g + 1], ah[mt], bl[g][2], bl[g][3]);
                }
        }
    }

    // epilogue: write fp32 logits
#pragma unroll
    for (int mt = 0; mt < 2; mt++) {
        const int gr = m0 + wm + mt * 16 + (lane >> 2);
#pragma unroll
        for (int nt = 0; nt < 4; nt++) {
            const int gc = n0 + wn + nt * 8 + (lane & 3) * 2;
            float2 v0 = {acc[mt][nt][0], acc[mt][nt][1]};
            float2 v1 = {acc[mt][nt][2], acc[mt][nt][3]};
            *(float2*)&g_logits[(size_t)gr * NEXP + gc]       = v0;
            *(float2*)&g_logits[(size_t)(gr + 8) * NEXP + gc] = v1;
        }
    }
}

// ---------------- routing (redux-based reductions) --------------------------
__global__ __launch_bounds__(256) void route_kernel(const float* __restrict__ bias,
                                                    float* __restrict__ out,
                                                    int out_size) {
    const int token = (blockIdx.x * blockDim.x + threadIdx.x) >> 5;
    const int lane  = threadIdx.x & 31;
    if (token >= B_TOK) return;
    const float* lg = g_logits + (size_t)token * NEXP;

    float v[NGRP];
#pragma unroll
    for (int j = 0; j < NGRP; j++) v[j] = lg[lane + 32 * j];

    // softmax over 256 (max via order-preserving uint transform + redux)
    float m = v[0];
#pragma unroll
    for (int j = 1; j < NGRP; j++) m = fmaxf(m, v[j]);
    {
        uint32_t b = __float_as_uint(m);
        uint32_t key = b ^ (((int32_t)b >> 31) | 0x80000000u);
        uint32_t mk = __reduce_max_sync(0xffffffffu, key);
        uint32_t mb = mk ^ (~((int32_t)(mk ^ 0x80000000u) >> 31) | 0x80000000u);
        // invert: if mk's sign bit set -> original positive (b = mk ^ 0x80000000)
        // else original negative (b = ~mk)
        mb = (mk & 0x80000000u) ? (mk ^ 0x80000000u) : ~mk;
        m = __uint_as_float(mb);
    }
    float s = 0.f, sc[NGRP];
#pragma unroll
    for (int j = 0; j < NGRP; j++) { sc[j] = __expf(v[j] - m); s += sc[j]; }
#pragma unroll
    for (int o = 16; o > 0; o >>= 1) s += __shfl_xor_sync(0xffffffffu, s, o);
    const float inv = 1.f / s;

    float swb[NGRP];   // strictly positive: sc>0, bias in [0,1)
#pragma unroll
    for (int j = 0; j < NGRP; j++) { sc[j] *= inv; swb[j] = sc[j] + bias[lane + 32 * j]; }

    // group score = top-2 sum (positive floats: uint-monotone)
    float gscore[NGRP];
#pragma unroll
    for (int j = 0; j < NGRP; j++) {
        uint32_t b  = __float_as_uint(swb[j]);
        uint32_t m1 = __reduce_max_sync(0xffffffffu, b);
        int l1 = __ffs(__ballot_sync(0xffffffffu, b == m1)) - 1;
        uint32_t b2 = (lane == l1) ? 0u : b;
        uint32_t m2 = __reduce_max_sync(0xffffffffu, b2);
        gscore[j] = __uint_as_float(m1) + __uint_as_float(m2);
    }

    float gtmp[NGRP]; bool gsel[NGRP];
#pragma unroll
    for (int j = 0; j < NGRP; j++) { gtmp[j] = gscore[j]; gsel[j] = false; }
#pragma unroll
    for (int t = 0; t < TOPKG; t++) {
        int best = 0; float bv = -CUDART_INF_F;
#pragma unroll
        for (int j = 0; j < NGRP; j++)
            if (gtmp[j] > bv) { bv = gtmp[j]; best = j; }
        gsel[best] = true; gtmp[best] = -CUDART_INF_F;
    }

    // masked: 0.0 sentinel (swb>0; 128 candidates >> 8 picks so never exhausted)
    float masked[NGRP];
#pragma unroll
    for (int j = 0; j < NGRP; j++) masked[j] = gsel[j] ? swb[j] : 0.f;

    float wv[TOPK]; int widx[TOPK]; float wsum = 0.f;
#pragma unroll
    for (int t = 0; t < TOPK; t++) {
        float bv = masked[0]; int bj = 0;
#pragma unroll
        for (int j = 1; j < NGRP; j++)
            if (masked[j] > bv) { bv = masked[j]; bj = j; }
        const uint32_t key = __float_as_uint(bv);
        const uint32_t mx  = __reduce_max_sync(0xffffffffu, key);
        const uint32_t cand = (key == mx) ? (uint32_t)(lane + 32 * bj) : 1024u;
        const int me = (int)__reduce_min_sync(0xffffffffu, cand);
        const int wl = me & 31, wj = me >> 5;
        float myv = sc[0];
#pragma unroll
        for (int j = 1; j < NGRP; j++) if (wj == j) myv = sc[j];
        float score = __shfl_sync(0xffffffffu, myv, wl);
        if (lane == wl) {
#pragma unroll
            for (int j = 0; j < NGRP; j++) if (wj == j) masked[j] = 0.f;
        }
        wv[t] = score; widx[t] = me; wsum += score;
    }

    if (lane == 0) {
        const float invw = 1.f / wsum;
#pragma unroll
        for (int t = 0; t < TOPK; t++)
            out[(size_t)token * TOPK + t] = (wv[t] * invw + EPS) * SCALE;
        if (out_size >= 2 * B_TOK * TOPK) {
#pragma unroll
            for (int t = 0; t < TOPK; t++)
                out[(size_t)B_TOK * TOPK + (size_t)token * TOPK + t] = (float)widx[t];
        }
    }
}

// ---------------------------------------------------------------------------
extern "C" void kernel_launch(void* const* d_in, const int* in_sizes, int n_in,
                              void* d_out, int out_size) {
    const float* x    = (const float*)d_in[0];
    const float* w    = (const float*)d_in[1];
    const float* bias = (const float*)d_in[2];
    float* out = (float*)d_out;

    cudaFuncSetAttribute(gemm_kernel, cudaFuncAttributeMaxDynamicSharedMemorySize, SMEM_GEMM);

    convert_w_kernel<<<dim3(HDIM / 32, NEXP / 32), dim3(32, 8)>>>(w);
    gemm_kernel<<<dim3(B_TOK / 128, 2), 512, SMEM_GEMM>>>(x);
    route_kernel<<<B_TOK / 8, 256>>>(bias, out, out_size);
}

// round 11
// speedup vs baseline: 1.1515x; 1.0654x over previous
#include <cuda_runtime.h>
#include <cuda_bf16.h>
#include <math_constants.h>
#include <cstdint>

#define B_TOK 8192
#define HDIM  7168
#define NEXP  256
#define NGRP  8
#define TOPKG 4
#define TOPK  8
#define SCALE 2.5f
#define EPS   1e-20f

// ---------------- static device scratch (allocation-free rule) -------------
__device__ __nv_bfloat16 g_wh[(size_t)NEXP * HDIM];   // transposed [E][H]
__device__ __nv_bfloat16 g_wl[(size_t)NEXP * HDIM];
__device__ float g_logits[(size_t)B_TOK * NEXP];

// ---------------- weight conversion ----------------------------------------
__global__ void convert_w_kernel(const float* __restrict__ w) {
    __shared__ float tile[32][33];
    const int k0 = blockIdx.x * 32, e0 = blockIdx.y * 32;
    const int tx = threadIdx.x, ty = threadIdx.y;   // block (32,8)
#pragma unroll
    for (int j = 0; j < 4; j++)
        tile[ty + j * 8][tx] = w[(size_t)(k0 + ty + j * 8) * NEXP + e0 + tx];
    __syncthreads();
#pragma unroll
    for (int j = 0; j < 4; j++) {
        float v = tile[tx][ty + j * 8];
        __nv_bfloat16 h = __float2bfloat16(v);
        size_t o = (size_t)(e0 + ty + j * 8) * HDIM + k0 + tx;
        g_wh[o] = h;
        g_wl[o] = __float2bfloat16(v - __bfloat162float(h));
    }
}

// ---------------- fused split + bf16 mma.sync GEMM --------------------------
// CTA 128x128, 32 warps of 16x32, BK=64, 3-stage pipeline, 1024 threads.
#define BK      64
#define PITCH   144
#define TILE_SM (128 * PITCH)              // 18432
#define STAGE_B (4 * TILE_SM)              // xh, xl, wh, wl = 73728
#define NSTAGE  3
#define SMEM_GEMM (NSTAGE * STAGE_B)       // 221184
#define NCHUNK  (HDIM / BK)                // 112

__device__ __forceinline__ uint32_t smem_u32(const void* p) {
    uint32_t a;
    asm("{ .reg .u64 t; cvta.to.shared.u64 t, %1; cvt.u32.u64 %0, t; }" : "=r"(a) : "l"(p));
    return a;
}
#define CP_ASYNC16(dst, src) \
    asm volatile("cp.async.cg.shared.global [%0], [%1], 16;" :: "r"(dst), "l"(src) : "memory")
#define CP_COMMIT() asm volatile("cp.async.commit_group;" ::: "memory")
#define CP_WAIT1()  asm volatile("cp.async.wait_group 1;" ::: "memory")

#define STS128(a, r0, r1, r2, r3) \
    asm volatile("st.shared.v4.b32 [%0], {%1,%2,%3,%4};" \
        :: "r"(a), "r"(r0), "r"(r1), "r"(r2), "r"(r3) : "memory")

#define LDMATRIX_X4(r0, r1, r2, r3, a) \
    asm volatile("ldmatrix.sync.aligned.m8n8.x4.shared.b16 {%0,%1,%2,%3}, [%4];" \
        : "=r"(r0), "=r"(r1), "=r"(r2), "=r"(r3) : "r"(a))

#define MMA_BF16(c, a0, a1, a2, a3, b0, b1) \
    asm volatile("mma.sync.aligned.m16n8k16.row.col.f32.bf16.bf16.f32 " \
        "{%0,%1,%2,%3}, {%4,%5,%6,%7}, {%8,%9}, {%0,%1,%2,%3};" \
        : "+f"((c)[0]), "+f"((c)[1]), "+f"((c)[2]), "+f"((c)[3]) \
        : "r"(a0), "r"(a1), "r"(a2), "r"(a3), "r"(b0), "r"(b1))

__device__ __forceinline__ uint32_t pack_bf16(float f0, float f1) {
    __nv_bfloat162 p;
    p.x = __float2bfloat16(f0);
    p.y = __float2bfloat16(f1);
    return *(uint32_t*)&p;
}

__global__ __launch_bounds__(1024, 1) void gemm_kernel(const float* __restrict__ x) {
    extern __shared__ char smem[];
    const uint32_t sbase = smem_u32(smem);
    const int tid  = threadIdx.x;
    const int wid  = tid >> 5;
    const int lane = tid & 31;
    const int m0   = blockIdx.x * 128;
    const int n0   = blockIdx.y * 128;
    const int wm   = (wid & 7) * 16;      // warp tile 16(M) x 32(N)
    const int wn   = (wid >> 3) * 32;

    float acc[4][4];
#pragma unroll
    for (int nt = 0; nt < 4; nt++)
#pragma unroll
        for (int r = 0; r < 4; r++) acc[nt][r] = 0.f;

    const int a_row = ((lane >> 3) & 1) * 8 + (lane & 7);
    const int a_k   = ((lane >> 4) & 1) * 8;
    const int b_row = ((lane >> 4) & 1) * 8 + (lane & 7);
    const int b_k   = ((lane >> 3) & 1) * 8;

    // producers over 1024 threads: row = tid>>3 (0..127), seg = tid&7
    const int prow = tid >> 3;
    const int pseg = tid & 7;

    auto ldgA = [&](int chunk, float4* buf) {
        const float* p = x + (size_t)(m0 + prow) * HDIM + chunk * BK + pseg * 8;
        buf[0] = *(const float4*)(p);
        buf[1] = *(const float4*)(p + 4);
    };
    auto stsA = [&](int stage, const float4* buf) {
        const float* a = (const float*)buf;
        uint32_t hh[4], ll[4];
#pragma unroll
        for (int j = 0; j < 4; j++) {
            float f0 = a[2 * j], f1 = a[2 * j + 1];
            __nv_bfloat16 h0 = __float2bfloat16(f0);
            __nv_bfloat16 h1 = __float2bfloat16(f1);
            hh[j] = ((uint32_t)*(uint16_t*)&h0) | ((uint32_t)*(uint16_t*)&h1 << 16);
            ll[j] = pack_bf16(f0 - __bfloat162float(h0), f1 - __bfloat162float(h1));
        }
        const uint32_t xh_s = sbase + stage * STAGE_B + prow * PITCH + pseg * 16;
        STS128(xh_s,           hh[0], hh[1], hh[2], hh[3]);
        STS128(xh_s + TILE_SM, ll[0], ll[1], ll[2], ll[3]);
    };
    auto cpB = [&](int chunk, int stage) {
        const size_t gof = (size_t)(n0 + prow) * HDIM + chunk * BK + pseg * 8;
        const uint32_t whs = sbase + stage * STAGE_B + 2 * TILE_SM + prow * PITCH + pseg * 16;
        CP_ASYNC16(whs,           g_wh + gof);
        CP_ASYNC16(whs + TILE_SM, g_wl + gof);
    };

    // prologue
    float4 abuf[2];
    {
        float4 t[2];
        ldgA(0, t); stsA(0, t); cpB(0, 0); CP_COMMIT();
        ldgA(1, t); stsA(1, t); cpB(1, 1); CP_COMMIT();
        ldgA(2, abuf);
    }

    for (int i = 0; i < NCHUNK; i++) {
        CP_WAIT1();
        __syncthreads();
        if (i + 2 < NCHUNK) { stsA((i + 2) % NSTAGE, abuf); cpB(i + 2, (i + 2) % NSTAGE); }
        if (i + 3 < NCHUNK) ldgA(i + 3, abuf);
        CP_COMMIT();

        const int s = i % NSTAGE;
        const uint32_t Ah = sbase + s * STAGE_B;
        const uint32_t Al = Ah + TILE_SM;
        const uint32_t Bh = Ah + 2 * TILE_SM;
        const uint32_t Bl = Ah + 3 * TILE_SM;
#pragma unroll
        for (int ki = 0; ki < BK; ki += 16) {
            uint32_t ah[4], al[4], bh[2][4], bl[2][4];
            const uint32_t aro = (wm + a_row) * PITCH + (a_k + ki) * 2;
            // batch 1: hi fragments, hh MMAs
            LDMATRIX_X4(ah[0], ah[1], ah[2], ah[3], Ah + aro);
#pragma unroll
            for (int g = 0; g < 2; g++) {
                const uint32_t ro = (wn + g * 16 + b_row) * PITCH + (b_k + ki) * 2;
                LDMATRIX_X4(bh[g][0], bh[g][1], bh[g][2], bh[g][3], Bh + ro);
            }
#pragma unroll
            for (int g = 0; g < 2; g++) {
                MMA_BF16(acc[2 * g],     ah[0], ah[1], ah[2], ah[3], bh[g][0], bh[g][1]);
                MMA_BF16(acc[2 * g + 1], ah[0], ah[1], ah[2], ah[3], bh[g][2], bh[g][3]);
            }
            // batch 2: lo fragments, lh + hl MMAs
            LDMATRIX_X4(al[0], al[1], al[2], al[3], Al + aro);
#pragma unroll
            for (int g = 0; g < 2; g++) {
                const uint32_t ro = (wn + g * 16 + b_row) * PITCH + (b_k + ki) * 2;
                LDMATRIX_X4(bl[g][0], bl[g][1], bl[g][2], bl[g][3], Bl + ro);
            }
#pragma unroll
            for (int g = 0; g < 2; g++) {
                MMA_BF16(acc[2 * g],     al[0], al[1], al[2], al[3], bh[g][0], bh[g][1]);
                MMA_BF16(acc[2 * g + 1], al[0], al[1], al[2], al[3], bh[g][2], bh[g][3]);
            }
#pragma unroll
            for (int g = 0; g < 2; g++) {
                MMA_BF16(acc[2 * g],     ah[0], ah[1], ah[2], ah[3], bl[g][0], bl[g][1]);
                MMA_BF16(acc[2 * g + 1], ah[0], ah[1], ah[2], ah[3], bl[g][2], bl[g][3]);
            }
        }
    }

    // epilogue: write fp32 logits
    {
        const int gr = m0 + wm + (lane >> 2);
#pragma unroll
        for (int nt = 0; nt < 4; nt++) {
            const int gc = n0 + wn + nt * 8 + (lane & 3) * 2;
            float2 v0 = {acc[nt][0], acc[nt][1]};
            float2 v1 = {acc[nt][2], acc[nt][3]};
            *(float2*)&g_logits[(size_t)gr * NEXP + gc]       = v0;
            *(float2*)&g_logits[(size_t)(gr + 8) * NEXP + gc] = v1;
        }
    }
}

// ---------------- routing (redux-based reductions) --------------------------
__global__ __launch_bounds__(256) void route_kernel(const float* __restrict__ bias,
                                                    float* __restrict__ out,
                                                    int out_size) {
    const int token = (blockIdx.x * blockDim.x + threadIdx.x) >> 5;
    const int lane  = threadIdx.x & 31;
    if (token >= B_TOK) return;
    const float* lg = g_logits + (size_t)token * NEXP;

    float v[NGRP];
#pragma unroll
    for (int j = 0; j < NGRP; j++) v[j] = lg[lane + 32 * j];

    float m = v[0];
#pragma unroll
    for (int j = 1; j < NGRP; j++) m = fmaxf(m, v[j]);
    {
        uint32_t b = __float_as_uint(m);
        uint32_t key = b ^ (((int32_t)b >> 31) | 0x80000000u);
        uint32_t mk = __reduce_max_sync(0xffffffffu, key);
        uint32_t mb = (mk & 0x80000000u) ? (mk ^ 0x80000000u) : ~mk;
        m = __uint_as_float(mb);
    }
    float s = 0.f, sc[NGRP];
#pragma unroll
    for (int j = 0; j < NGRP; j++) { sc[j] = __expf(v[j] - m); s += sc[j]; }
#pragma unroll
    for (int o = 16; o > 0; o >>= 1) s += __shfl_xor_sync(0xffffffffu, s, o);
    const float inv = 1.f / s;

    float swb[NGRP];   // strictly positive: sc>0, bias in [0,1)
#pragma unroll
    for (int j = 0; j < NGRP; j++) { sc[j] *= inv; swb[j] = sc[j] + bias[lane + 32 * j]; }

    float gscore[NGRP];
#pragma unroll
    for (int j = 0; j < NGRP; j++) {
        uint32_t b  = __float_as_uint(swb[j]);
        uint32_t m1 = __reduce_max_sync(0xffffffffu, b);
        int l1 = __ffs(__ballot_sync(0xffffffffu, b == m1)) - 1;
        uint32_t b2 = (lane == l1) ? 0u : b;
        uint32_t m2 = __reduce_max_sync(0xffffffffu, b2);
        gscore[j] = __uint_as_float(m1) + __uint_as_float(m2);
    }

    float gtmp[NGRP]; bool gsel[NGRP];
#pragma unroll
    for (int j = 0; j < NGRP; j++) { gtmp[j] = gscore[j]; gsel[j] = false; }
#pragma unroll
    for (int t = 0; t < TOPKG; t++) {
        int best = 0; float bv = -CUDART_INF_F;
#pragma unroll
        for (int j = 0; j < NGRP; j++)
            if (gtmp[j] > bv) { bv = gtmp[j]; best = j; }
        gsel[best] = true; gtmp[best] = -CUDART_INF_F;
    }

    float masked[NGRP];
#pragma unroll
    for (int j = 0; j < NGRP; j++) masked[j] = gsel[j] ? swb[j] : 0.f;

    float wv[TOPK]; int widx[TOPK]; float wsum = 0.f;
#pragma unroll
    for (int t = 0; t < TOPK; t++) {
        float bv = masked[0]; int bj = 0;
#pragma unroll
        for (int j = 1; j < NGRP; j++)
            if (masked[j] > bv) { bv = masked[j]; bj = j; }
        const uint32_t key = __float_as_uint(bv);
        const uint32_t mx  = __reduce_max_sync(0xffffffffu, key);
        const uint32_t cand = (key == mx) ? (uint32_t)(lane + 32 * bj) : 1024u;
        const int me = (int)__reduce_min_sync(0xffffffffu, cand);
        const int wl = me & 31, wj = me >> 5;
        float myv = sc[0];
#pragma unroll
        for (int j = 1; j < NGRP; j++) if (wj == j) myv = sc[j];
        float score = __shfl_sync(0xffffffffu, myv, wl);
        if (lane == wl) {
#pragma unroll
            for (int j = 0; j < NGRP; j++) if (wj == j) masked[j] = 0.f;
        }
        wv[t] = score; widx[t] = me; wsum += score;
    }

    if (lane == 0) {
        const float invw = 1.f / wsum;
#pragma unroll
        for (int t = 0; t < TOPK; t++)
            out[(size_t)token * TOPK + t] = (wv[t] * invw + EPS) * SCALE;
        if (out_size >= 2 * B_TOK * TOPK) {
#pragma unroll
            for (int t = 0; t < TOPK; t++)
                out[(size_t)B_TOK * TOPK + (size_t)token * TOPK + t] = (float)widx[t];
        }
    }
}

// ---------------------------------------------------------------------------
extern "C" void kernel_launch(void* const* d_in, const int* in_sizes, int n_in,
                              void* d_out, int out_size) {
    const float* x    = (const float*)d_in[0];
    const float* w    = (const float*)d_in[1];
    const float* bias = (const float*)d_in[2];
    float* out = (float*)d_out;

    cudaFuncSetAttribute(gemm_kernel, cudaFuncAttributeMaxDynamicSharedMemorySize, SMEM_GEMM);

    convert_w_kernel<<<dim3(HDIM / 32, NEXP / 32), dim3(32, 8)>>>(w);
    gemm_kernel<<<dim3(B_TOK / 128, 2), 1024, SMEM_GEMM>>>(x);
    route_kernel<<<B_TOK / 8, 256>>>(bias, out, out_size);
}

// round 12
// speedup vs baseline: 1.5168x; 1.3172x over previous
#include <cuda_runtime.h>
#include <cuda_bf16.h>
#include <math_constants.h>
#include <cstdint>

#define B_TOK 8192
#define HDIM  7168
#define NEXP  256
#define NGRP  8
#define TOPKG 4
#define TOPK  8
#define SCALE 2.5f
#define EPS   1e-20f

// ---------------- static device scratch (allocation-free rule) -------------
__device__ __nv_bfloat16 g_wh[(size_t)NEXP * HDIM];   // transposed [E][H]
__device__ __nv_bfloat16 g_wl[(size_t)NEXP * HDIM];
__device__ float g_logits[(size_t)B_TOK * NEXP];

// ---------------- weight conversion ----------------------------------------
__global__ void convert_w_kernel(const float* __restrict__ w) {
    __shared__ float tile[32][33];
    const int k0 = blockIdx.x * 32, e0 = blockIdx.y * 32;
    const int tx = threadIdx.x, ty = threadIdx.y;   // block (32,8)
#pragma unroll
    for (int j = 0; j < 4; j++)
        tile[ty + j * 8][tx] = w[(size_t)(k0 + ty + j * 8) * NEXP + e0 + tx];
    __syncthreads();
#pragma unroll
    for (int j = 0; j < 4; j++) {
        float v = tile[tx][ty + j * 8];
        __nv_bfloat16 h = __float2bfloat16(v);
        size_t o = (size_t)(e0 + ty + j * 8) * HDIM + k0 + tx;
        g_wh[o] = h;
        g_wl[o] = __float2bfloat16(v - __bfloat162float(h));
    }
}

// ---------------- fused split + bf16 mma.sync GEMM, ragged split-K ----------
// 148 persistent CTAs; work = 128 tiles (64 M x 2 N) x 112 chunks, linearized.
#define BK      64
#define PITCH   144
#define TILE_SM (128 * PITCH)              // 18432
#define STAGE_B (4 * TILE_SM)              // xh, xl, wh, wl = 73728
#define NSTAGE  3
#define SMEM_GEMM (NSTAGE * STAGE_B)       // 221184
#define NCH     (HDIM / BK)                // 112 chunks per tile
#define NTILES  128
#define TOTWORK (NTILES * NCH)             // 14336
#define NCTAS   148

__device__ __forceinline__ uint32_t smem_u32(const void* p) {
    uint32_t a;
    asm("{ .reg .u64 t; cvta.to.shared.u64 t, %1; cvt.u32.u64 %0, t; }" : "=r"(a) : "l"(p));
    return a;
}
#define CP_ASYNC16(dst, src) \
    asm volatile("cp.async.cg.shared.global [%0], [%1], 16;" :: "r"(dst), "l"(src) : "memory")
#define CP_COMMIT() asm volatile("cp.async.commit_group;" ::: "memory")
#define CP_WAIT1()  asm volatile("cp.async.wait_group 1;" ::: "memory")
#define CP_WAIT0()  asm volatile("cp.async.wait_group 0;" ::: "memory")

#define STS128(a, r0, r1, r2, r3) \
    asm volatile("st.shared.v4.b32 [%0], {%1,%2,%3,%4};" \
        :: "r"(a), "r"(r0), "r"(r1), "r"(r2), "r"(r3) : "memory")

#define LDMATRIX_X4(r0, r1, r2, r3, a) \
    asm volatile("ldmatrix.sync.aligned.m8n8.x4.shared.b16 {%0,%1,%2,%3}, [%4];" \
        : "=r"(r0), "=r"(r1), "=r"(r2), "=r"(r3) : "r"(a))

#define MMA_BF16(c, a0, a1, a2, a3, b0, b1) \
    asm volatile("mma.sync.aligned.m16n8k16.row.col.f32.bf16.bf16.f32 " \
        "{%0,%1,%2,%3}, {%4,%5,%6,%7}, {%8,%9}, {%0,%1,%2,%3};" \
        : "+f"((c)[0]), "+f"((c)[1]), "+f"((c)[2]), "+f"((c)[3]) \
        : "r"(a0), "r"(a1), "r"(a2), "r"(a3), "r"(b0), "r"(b1))

__device__ __forceinline__ uint32_t pack_bf16(float f0, float f1) {
    __nv_bfloat162 p;
    p.x = __float2bfloat16(f0);
    p.y = __float2bfloat16(f1);
    return *(uint32_t*)&p;
}

__global__ __launch_bounds__(1024, 1) void gemm_kernel(const float* __restrict__ x) {
    extern __shared__ char smem[];
    const uint32_t sbase = smem_u32(smem);
    const int tid  = threadIdx.x;
    const int wid  = tid >> 5;
    const int lane = tid & 31;
    const int wm   = (wid & 7) * 16;      // warp tile 16(M) x 32(N)
    const int wn   = (wid >> 3) * 32;

    const int a_row = ((lane >> 3) & 1) * 8 + (lane & 7);
    const int a_k   = ((lane >> 4) & 1) * 8;
    const int b_row = ((lane >> 4) & 1) * 8 + (lane & 7);
    const int b_k   = ((lane >> 3) & 1) * 8;

    const int prow = tid >> 3;
    const int pseg = tid & 7;

    int s = (int)(((long long)blockIdx.x * TOTWORK) / NCTAS);
    const int e = (int)(((long long)(blockIdx.x + 1) * TOTWORK) / NCTAS);

    while (s < e) {
        const int t    = s / NCH;
        const int c0   = s - t * NCH;
        const int ce   = min(e - t * NCH, NCH);
        const int n    = ce - c0;
        const int m0   = (t >> 1) * 128;
        const int n0   = (t & 1) * 128;
        s = t * NCH + ce;

        float acc[4][4];
#pragma unroll
        for (int nt = 0; nt < 4; nt++)
#pragma unroll
            for (int r = 0; r < 4; r++) acc[nt][r] = 0.f;

        auto ldgA = [&](int chunk, float4* buf) {
            const float* p = x + (size_t)(m0 + prow) * HDIM + chunk * BK + pseg * 8;
            buf[0] = *(const float4*)(p);
            buf[1] = *(const float4*)(p + 4);
        };
        auto stsA = [&](int stage, const float4* buf) {
            const float* a = (const float*)buf;
            uint32_t hh[4], ll[4];
#pragma unroll
            for (int j = 0; j < 4; j++) {
                float f0 = a[2 * j], f1 = a[2 * j + 1];
                __nv_bfloat16 h0 = __float2bfloat16(f0);
                __nv_bfloat16 h1 = __float2bfloat16(f1);
                hh[j] = ((uint32_t)*(uint16_t*)&h0) | ((uint32_t)*(uint16_t*)&h1 << 16);
                ll[j] = pack_bf16(f0 - __bfloat162float(h0), f1 - __bfloat162float(h1));
            }
            const uint32_t xh_s = sbase + stage * STAGE_B + prow * PITCH + pseg * 16;
            STS128(xh_s,           hh[0], hh[1], hh[2], hh[3]);
            STS128(xh_s + TILE_SM, ll[0], ll[1], ll[2], ll[3]);
        };
        auto cpB = [&](int chunk, int stage) {
            const size_t gof = (size_t)(n0 + prow) * HDIM + chunk * BK + pseg * 8;
            const uint32_t whs = sbase + stage * STAGE_B + 2 * TILE_SM + prow * PITCH + pseg * 16;
            CP_ASYNC16(whs,           g_wh + gof);
            CP_ASYNC16(whs + TILE_SM, g_wl + gof);
        };

        // prologue
        float4 abuf[2];
        {
            float4 t4[2];
            ldgA(c0, t4); stsA(0, t4); cpB(c0, 0); CP_COMMIT();
            if (n > 1) { ldgA(c0 + 1, t4); stsA(1, t4); cpB(c0 + 1, 1); }
            CP_COMMIT();
            if (n > 2) ldgA(c0 + 2, abuf);
        }

        for (int j = 0; j < n; j++) {
            CP_WAIT1();
            __syncthreads();
            if (j + 2 < n) { stsA((j + 2) % NSTAGE, abuf); cpB(c0 + j + 2, (j + 2) % NSTAGE); }
            if (j + 3 < n) ldgA(c0 + j + 3, abuf);
            CP_COMMIT();

            const int st = j % NSTAGE;
            const uint32_t Ah = sbase + st * STAGE_B;
            const uint32_t Al = Ah + TILE_SM;
            const uint32_t Bh = Ah + 2 * TILE_SM;
            const uint32_t Bl = Ah + 3 * TILE_SM;
#pragma unroll
            for (int ki = 0; ki < BK; ki += 16) {
                uint32_t ah[4], al[4], bh[2][4], bl[2][4];
                const uint32_t aro = (wm + a_row) * PITCH + (a_k + ki) * 2;
                LDMATRIX_X4(ah[0], ah[1], ah[2], ah[3], Ah + aro);
#pragma unroll
                for (int g = 0; g < 2; g++) {
                    const uint32_t ro = (wn + g * 16 + b_row) * PITCH + (b_k + ki) * 2;
                    LDMATRIX_X4(bh[g][0], bh[g][1], bh[g][2], bh[g][3], Bh + ro);
                }
#pragma unroll
                for (int g = 0; g < 2; g++) {
                    MMA_BF16(acc[2 * g],     ah[0], ah[1], ah[2], ah[3], bh[g][0], bh[g][1]);
                    MMA_BF16(acc[2 * g + 1], ah[0], ah[1], ah[2], ah[3], bh[g][2], bh[g][3]);
                }
                LDMATRIX_X4(al[0], al[1], al[2], al[3], Al + aro);
#pragma unroll
                for (int g = 0; g < 2; g++) {
                    const uint32_t ro = (wn + g * 16 + b_row) * PITCH + (b_k + ki) * 2;
                    LDMATRIX_X4(bl[g][0], bl[g][1], bl[g][2], bl[g][3], Bl + ro);
                }
#pragma unroll
                for (int g = 0; g < 2; g++) {
                    MMA_BF16(acc[2 * g],     al[0], al[1], al[2], al[3], bh[g][0], bh[g][1]);
                    MMA_BF16(acc[2 * g + 1], al[0], al[1], al[2], al[3], bh[g][2], bh[g][3]);
                }
#pragma unroll
                for (int g = 0; g < 2; g++) {
                    MMA_BF16(acc[2 * g],     ah[0], ah[1], ah[2], ah[3], bl[g][0], bl[g][1]);
                    MMA_BF16(acc[2 * g + 1], ah[0], ah[1], ah[2], ah[3], bl[g][2], bl[g][3]);
                }
            }
        }

        // drain before smem reuse by next segment
        CP_WAIT0();
        __syncthreads();

        // epilogue: accumulate partial into g_logits (zeroed before launch)
        {
            const int gr = m0 + wm + (lane >> 2);
#pragma unroll
            for (int nt = 0; nt < 4; nt++) {
                const int gc = n0 + wn + nt * 8 + (lane & 3) * 2;
                atomicAdd(&g_logits[(size_t)gr * NEXP + gc],           acc[nt][0]);
                atomicAdd(&g_logits[(size_t)gr * NEXP + gc + 1],       acc[nt][1]);
                atomicAdd(&g_logits[(size_t)(gr + 8) * NEXP + gc],     acc[nt][2]);
                atomicAdd(&g_logits[(size_t)(gr + 8) * NEXP + gc + 1], acc[nt][3]);
            }
        }
    }
}

// ---------------- routing (redux-based reductions) --------------------------
__global__ __launch_bounds__(256) void route_kernel(const float* __restrict__ bias,
                                                    float* __restrict__ out,
                                                    int out_size) {
    const int token = (blockIdx.x * blockDim.x + threadIdx.x) >> 5;
    const int lane  = threadIdx.x & 31;
    if (token >= B_TOK) return;
    const float* lg = g_logits + (size_t)token * NEXP;

    float v[NGRP];
#pragma unroll
    for (int j = 0; j < NGRP; j++) v[j] = lg[lane + 32 * j];

    float m = v[0];
#pragma unroll
    for (int j = 1; j < NGRP; j++) m = fmaxf(m, v[j]);
    {
        uint32_t b = __float_as_uint(m);
        uint32_t key = b ^ (((int32_t)b >> 31) | 0x80000000u);
        uint32_t mk = __reduce_max_sync(0xffffffffu, key);
        uint32_t mb = (mk & 0x80000000u) ? (mk ^ 0x80000000u) : ~mk;
        m = __uint_as_float(mb);
    }
    float s = 0.f, sc[NGRP];
#pragma unroll
    for (int j = 0; j < NGRP; j++) { sc[j] = __expf(v[j] - m); s += sc[j]; }
#pragma unroll
    for (int o = 16; o > 0; o >>= 1) s += __shfl_xor_sync(0xffffffffu, s, o);
    const float inv = 1.f / s;

    float swb[NGRP];   // strictly positive: sc>0, bias in [0,1)
#pragma unroll
    for (int j = 0; j < NGRP; j++) { sc[j] *= inv; swb[j] = sc[j] + bias[lane + 32 * j]; }

    float gscore[NGRP];
#pragma unroll
    for (int j = 0; j < NGRP; j++) {
        uint32_t b  = __float_as_uint(swb[j]);
        uint32_t m1 = __reduce_max_sync(0xffffffffu, b);
        int l1 = __ffs(__ballot_sync(0xffffffffu, b == m1)) - 1;
        uint32_t b2 = (lane == l1) ? 0u : b;
        uint32_t m2 = __reduce_max_sync(0xffffffffu, b2);
        gscore[j] = __uint_as_float(m1) + __uint_as_float(m2);
    }

    float gtmp[NGRP]; bool gsel[NGRP];
#pragma unroll
    for (int j = 0; j < NGRP; j++) { gtmp[j] = gscore[j]; gsel[j] = false; }
#pragma unroll
    for (int t = 0; t < TOPKG; t++) {
        int best = 0; float bv = -CUDART_INF_F;
#pragma unroll
        for (int j = 0; j < NGRP; j++)
            if (gtmp[j] > bv) { bv = gtmp[j]; best = j; }
        gsel[best] = true; gtmp[best] = -CUDART_INF_F;
    }

    float masked[NGRP];
#pragma unroll
    for (int j = 0; j < NGRP; j++) masked[j] = gsel[j] ? swb[j] : 0.f;

    float wv[TOPK]; int widx[TOPK]; float wsum = 0.f;
#pragma unroll
    for (int t = 0; t < TOPK; t++) {
        float bv = masked[0]; int bj = 0;
#pragma unroll
        for (int j = 1; j < NGRP; j++)
            if (masked[j] > bv) { bv = masked[j]; bj = j; }
        const uint32_t key = __float_as_uint(bv);
        const uint32_t mx  = __reduce_max_sync(0xffffffffu, key);
        const uint32_t cand = (key == mx) ? (uint32_t)(lane + 32 * bj) : 1024u;
        const int me = (int)__reduce_min_sync(0xffffffffu, cand);
        const int wl = me & 31, wj = me >> 5;
        float myv = sc[0];
#pragma unroll
        for (int j = 1; j < NGRP; j++) if (wj == j) myv = sc[j];
        float score = __shfl_sync(0xffffffffu, myv, wl);
        if (lane == wl) {
#pragma unroll
            for (int j = 0; j < NGRP; j++) if (wj == j) masked[j] = 0.f;
        }
        wv[t] = score; widx[t] = me; wsum += score;
    }

    if (lane == 0) {
        const float invw = 1.f / wsum;
#pragma unroll
        for (int t = 0; t < TOPK; t++)
            out[(size_t)token * TOPK + t] = (wv[t] * invw + EPS) * SCALE;
        if (out_size >= 2 * B_TOK * TOPK) {
#pragma unroll
            for (int t = 0; t < TOPK; t++)
                out[(size_t)B_TOK * TOPK + (size_t)token * TOPK + t] = (float)widx[t];
        }
    }
}

// ---------------------------------------------------------------------------
extern "C" void kernel_launch(void* const* d_in, const int* in_sizes, int n_in,
                              void* d_out, int out_size) {
    const float* x    = (const float*)d_in[0];
    const float* w    = (const float*)d_in[1];
    const float* bias = (const float*)d_in[2];
    float* out = (float*)d_out;

    void* p_logits = nullptr;
    cudaGetSymbolAddress(&p_logits, g_logits);

    cudaFuncSetAttribute(gemm_kernel, cudaFuncAttributeMaxDynamicSharedMemorySize, SMEM_GEMM);

    cudaMemsetAsync(p_logits, 0, (size_t)B_TOK * NEXP * sizeof(float));
    convert_w_kernel<<<dim3(HDIM / 32, NEXP / 32), dim3(32, 8)>>>(w);
    gemm_kernel<<<NCTAS, 1024, SMEM_GEMM>>>(x);
    route_kernel<<<B_TOK / 8, 256>>>(bias, out, out_size);
}